// round 8
// baseline (speedup 1.0000x reference)
#include <cuda_runtime.h>
#include <cuda_fp16.h>

// Problem constants
#define S      2785
#define S16    (S * 16)
#define G      689
#define NC     512            // batch chunks of 16
#define CAP    192            // max nnz per column
#define CAPP   (CAP / 2)      // entry pairs
#define NLAY   7
#define RSPLIT 8
#define NB     349            // column blocks of 8
#define NBP8   (NB * 8)
#define NFULL  444            // CTAs 0..443: full chunks 0..443
#define NHALF  136            // CTAs 444..579: half-chunks of chunks 444..511
#define NGRID  (NFULL + NHALF)
#define SSTRIDE 40            // smem bytes/slot: gcd(40,128)=8 -> 16 bank-start positions

// ---------------- device global scratch ---------------------------------------
__device__ __half g_actA[(size_t)NC * S16];   // activations fp16 ping
__device__ __half g_actB[(size_t)NC * S16];   // activations fp16 pong
__device__ float  g_Y[(size_t)NC * S16];      // raw pre-BN layer output fp32
__device__ int4   g_be2[(size_t)NLAY * NB * CAPP * 8]; // paired entries [l][b][kp][g]
__device__ float2 g_part[(size_t)S * NC];     // per (j, chunk) {sum, sumsq}
__device__ float4 g_stat[S];                  // {mean, gamma*rstd, beta, d}
__device__ int    g_cnt[NLAY * S];
__device__ int    g_cnt8[NLAY * RSPLIT * S];
__device__ int    g_off8[NLAY * RSPLIT * S];
__device__ int    g_perm[NLAY * NBP8];
__device__ int    g_scnt[NLAY * NBP8];
__device__ int    g_blkmax[NLAY * NB];

__device__ __forceinline__ __half* getact(int s) { return s == 0 ? g_actA : g_actB; }

// ---------------- build phase A: per-row-chunk nnz counts --------------------
__global__ void count_kernel(const float* __restrict__ lm0, const float* __restrict__ lm) {
    int l = blockIdx.y, r = blockIdx.z;
    int j = blockIdx.x * 128 + threadIdx.x;
    if (j >= S) return;
    int rows = (l == 0) ? G : S;
    const float* M = (l == 0) ? lm0 : lm + (size_t)(l - 1) * S * S;
    int chunk = (rows + RSPLIT - 1) / RSPLIT;
    int i0 = r * chunk;
    int i1 = min(rows, i0 + chunk);
    int c = 0;
    #pragma unroll 8
    for (int i = i0; i < i1; i++)
        c += (M[(size_t)i * S + j] != 0.f);
    g_cnt8[(l * RSPLIT + r) * S + j] = c;
}

// ---------------- build phase B: prefix offsets per column -------------------
__global__ void prefix_kernel() {
    int l = blockIdx.y;
    int j = blockIdx.x * 128 + threadIdx.x;
    if (j >= S) return;
    int off = 0;
    #pragma unroll
    for (int r = 0; r < RSPLIT; r++) {
        int c = g_cnt8[(l * RSPLIT + r) * S + j];
        g_off8[(l * RSPLIT + r) * S + j] = off;
        off += c;
    }
    g_cnt[l * S + j] = min(off, CAP);
}

// ---------------- build phase C: deterministic rank-sort (desc nnz, asc j) ---
#define S4 ((S + 3) / 4)
__global__ __launch_bounds__(1024)
void sort_kernel() {
    int l = blockIdx.y;
    __shared__ int4 scnt4[S4];
    int* scnt = (int*)scnt4;
    for (int j = threadIdx.x; j < S4 * 4; j += 1024)
        scnt[j] = (j < S) ? g_cnt[l * S + j] : -1;
    __syncthreads();

    int j = blockIdx.x * 1024 + threadIdx.x;
    if (j < S) {
        int c = scnt[j];
        int pos = 0;
        for (int q = 0; q < S4; q++) {
            int4 v = scnt4[q];
            int b0 = 4 * q;
            pos += (v.x > c) || (v.x == c && b0 + 0 < j);
            pos += (v.y > c) || (v.y == c && b0 + 1 < j);
            pos += (v.z > c) || (v.z == c && b0 + 2 < j);
            pos += (v.w > c) || (v.w == c && b0 + 3 < j);
        }
        g_perm[l * NBP8 + pos] = j;
        g_scnt[l * NBP8 + pos] = c;
        if ((pos & 7) == 0) g_blkmax[l * NB + (pos >> 3)] = c;
    }
    if (blockIdx.x == 0)
        for (int p = S + threadIdx.x; p < NBP8; p += 1024) {
            g_perm[l * NBP8 + p] = -1;
            g_scnt[l * NBP8 + p] = 0;
        }
}

// ---------------- build phase D: fill entries + zero-pad (row order kept) ----
__global__ void fill_kernel(const float* __restrict__ lm0, const float* __restrict__ W0,
                            const float* __restrict__ lm,  const float* __restrict__ Wl) {
    int l = blockIdx.y, r = blockIdx.z;
    int p = blockIdx.x * 128 + threadIdx.x;
    if (p >= NBP8) return;
    int j = g_perm[l * NBP8 + p];
    int b = p >> 3, g = p & 7;
    int2* e2 = (int2*)g_be2;
    size_t bi = (size_t)(l * NB + b) * CAPP;
    int km = g_blkmax[l * NB + b];
    int kmpad = ((km + 1) >> 1) << 1;

    if (j < 0) {   // pad column: zero everything once (from the r==last block)
        if (r == RSPLIT - 1)
            for (int k = 0; k < kmpad; k++)
                e2[((bi + (k >> 1)) * 8 + g) * 2 + (k & 1)] = make_int2(0, 0);
        return;
    }
    int rows; const float* M; const float* Wm;
    if (l == 0) { rows = G; M = lm0; Wm = W0; }
    else {
        size_t off0 = (size_t)(l - 1) * S * S;
        rows = S; M = lm + off0; Wm = Wl + off0;
    }
    int chunk = (rows + RSPLIT - 1) / RSPLIT;
    int i0 = r * chunk;
    int i1 = min(rows, i0 + chunk);
    int o = g_off8[(l * RSPLIT + r) * S + j];
    #pragma unroll 4
    for (int i = i0; i < i1; i++) {
        float m = M[(size_t)i * S + j];
        if (m != 0.f) {
            if (o < CAP) {
                float w = Wm[(size_t)i * S + j];
                e2[((bi + (o >> 1)) * 8 + g) * 2 + (o & 1)] =
                    make_int2(i * SSTRIDE, __float_as_int(w));
            }
            o++;
        }
    }
    if (r == RSPLIT - 1) {   // o is this column's total nnz; pad to kmpad
        int start = min(o, CAP);
        for (int k = start; k < kmpad; k++)
            e2[((bi + (k >> 1)) * 8 + g) * 2 + (k & 1)] = make_int2(0, 0);
    }
}

// ---------------- coalesced transpose x [B,G] -> [NC][G][16] fp16 ------------
#define XT_TI 128
__global__ __launch_bounds__(256)
void xt_kernel(const float* __restrict__ x) {
    __shared__ float tile[16][XT_TI + 1];
    int c  = blockIdx.y;
    int i0 = blockIdx.x * XT_TI;
    int t  = threadIdx.x;
    int col = t & 127;
    #pragma unroll
    for (int rr = 0; rr < 8; rr++) {
        int row = rr * 2 + (t >> 7);
        int i = i0 + col;
        tile[row][col] = (i < G) ? x[(size_t)(c * 16 + row) * G + i] : 0.f;
    }
    __syncthreads();
    int lane = t & 15;
    #pragma unroll
    for (int bq = 0; bq < 8; bq++) {
        int ii = (t >> 4) + bq * 16;
        int i = i0 + ii;
        if (i < G)
            g_actA[(size_t)c * (G * 16) + (size_t)i * 16 + lane] =
                __float2half_rn(tile[lane][ii]);
    }
}

// ---------------- fused SpMM: [BN+tanh+skip tile-load] + sparse gather + stats
__global__ __launch_bounds__(1024, 1)
void spmm_kernel(int mode, int wsel, int ssel, int layer, int n_slots) {
    extern __shared__ char xs[];

    int w     = threadIdx.x >> 5;
    int lane  = threadIdx.x & 31;
    int g     = lane >> 2;
    int lane4 = lane & 3;
    const char* xsb = xs + lane4 * 8;

    int bid = blockIdx.x;
    int c, b0, bstep;
    if (bid < NFULL) { c = bid; b0 = w; bstep = 32; }
    else {
        int t = bid - NFULL;
        c = NFULL + (t >> 1);
        b0 = (t & 1) + 2 * w;
        bstep = 64;
    }

    if (mode == 0) {
        const uint2* src = (const uint2*)(g_actA + (size_t)c * n_slots * 16);
        int nq = n_slots * 4;
        for (int t = threadIdx.x; t < nq; t += 1024) {
            int slot = t >> 2, q = t & 3;
            *(uint2*)(xs + slot * SSTRIDE + q * 8) = src[t];
        }
    } else {
        const float* Yc = g_Y + (size_t)c * S16;
        const __half* skp = getact(ssel) + (size_t)c * S16;
        __half* actw = getact(wsel) + (size_t)c * S16;
        for (int q = threadIdx.x; q < S * 4; q += 1024) {
            int slot = q >> 2, quad = q & 3;
            float4 st = g_stat[slot];                 // {m, gs, bt, d}
            float4 y  = *(const float4*)(Yc + slot * 16 + quad * 4);
            uint2 sk  = *(const uint2*)(skp + slot * 16 + quad * 4);
            float2 s0 = __half22float2(*(__half2*)&sk.x);
            float2 s1 = __half22float2(*(__half2*)&sk.y);
            float a0 = tanhf((y.x - st.x) * st.y + st.z) + s0.x * st.w;
            float a1 = tanhf((y.y - st.x) * st.y + st.z) + s0.y * st.w;
            float a2 = tanhf((y.z - st.x) * st.y + st.z) + s1.x * st.w;
            float a3 = tanhf((y.w - st.x) * st.y + st.z) + s1.y * st.w;
            __half2 h0 = __floats2half2_rn(a0, a1);
            __half2 h1 = __floats2half2_rn(a2, a3);
            uint2 pk;
            *(__half2*)&pk.x = h0;
            *(__half2*)&pk.y = h1;
            *(uint2*)(xs + slot * SSTRIDE + quad * 8) = pk;
            *(uint2*)(actw + slot * 16 + quad * 4) = pk;  // dup writes on split chunks: identical bits
        }
    }
    __syncthreads();

    float* yb = g_Y + (size_t)c * S16;
    for (int b = b0; b < NB; b += bstep) {
        int pp = b * 8 + g;
        int j  = g_perm[layer * NBP8 + pp];
        int km = g_blkmax[layer * NB + b];
        int kmp = (km + 1) >> 1;
        const int4* ep4 = g_be2 + (size_t)(layer * NB + b) * CAPP * 8 + g;
        float4 acc = make_float4(0.f, 0.f, 0.f, 0.f);
        if (kmp > 0) {
            // 2-deep entry prefetch: LDG for pair k+2 in flight while pair k's
            // FMAs run; LDS for pair k+1 uses an entry fetched a full iter ago.
            int4 e0 = ep4[0];
            int4 e1 = ep4[(size_t)min(1, kmp - 1) * 8];
            uint2 r0 = *(const uint2*)(xsb + e0.x);
            uint2 r1 = *(const uint2*)(xsb + e0.z);
            for (int kp = 0; kp + 1 < kmp; kp++) {
                int idx2 = min(kp + 2, kmp - 1);
                int4 en = ep4[(size_t)idx2 * 8];
                uint2 n0 = *(const uint2*)(xsb + e1.x);
                uint2 n1 = *(const uint2*)(xsb + e1.z);
                float w0 = __int_as_float(e0.y);
                float w1 = __int_as_float(e0.w);
                float2 a0 = __half22float2(*(__half2*)&r0.x);
                float2 a1 = __half22float2(*(__half2*)&r0.y);
                float2 b0v = __half22float2(*(__half2*)&r1.x);
                float2 b1v = __half22float2(*(__half2*)&r1.y);
                acc.x = fmaf(w0, a0.x, acc.x);
                acc.y = fmaf(w0, a0.y, acc.y);
                acc.z = fmaf(w0, a1.x, acc.z);
                acc.w = fmaf(w0, a1.y, acc.w);
                acc.x = fmaf(w1, b0v.x, acc.x);
                acc.y = fmaf(w1, b0v.y, acc.y);
                acc.z = fmaf(w1, b1v.x, acc.z);
                acc.w = fmaf(w1, b1v.y, acc.w);
                e0 = e1; e1 = en; r0 = n0; r1 = n1;
            }
            {
                float w0 = __int_as_float(e0.y);
                float w1 = __int_as_float(e0.w);
                float2 a0 = __half22float2(*(__half2*)&r0.x);
                float2 a1 = __half22float2(*(__half2*)&r0.y);
                float2 b0v = __half22float2(*(__half2*)&r1.x);
                float2 b1v = __half22float2(*(__half2*)&r1.y);
                acc.x = fmaf(w0, a0.x, acc.x);
                acc.y = fmaf(w0, a0.y, acc.y);
                acc.z = fmaf(w0, a1.x, acc.z);
                acc.w = fmaf(w0, a1.y, acc.w);
                acc.x = fmaf(w1, b0v.x, acc.x);
                acc.y = fmaf(w1, b0v.y, acc.y);
                acc.z = fmaf(w1, b1v.x, acc.z);
                acc.w = fmaf(w1, b1v.y, acc.w);
            }
        }
        // BN partials: shuffles MUST run convergent (pad lanes j==-1 included).
        float s  = acc.x + acc.y + acc.z + acc.w;
        float ss = acc.x * acc.x + acc.y * acc.y + acc.z * acc.z + acc.w * acc.w;
        s  += __shfl_xor_sync(0xffffffffu, s, 1);
        ss += __shfl_xor_sync(0xffffffffu, ss, 1);
        s  += __shfl_xor_sync(0xffffffffu, s, 2);
        ss += __shfl_xor_sync(0xffffffffu, ss, 2);
        if (j >= 0) {
            *(float4*)(yb + (size_t)j * 16 + lane4 * 4) = acc;
            if (lane4 == 0)
                g_part[(size_t)j * NC + c] = make_float2(s, ss);
        }
    }
}

// ---------------- stats: fold partials + gamma/beta/diag into float4 ---------
__global__ __launch_bounds__(256)
void stats_kernel(const float* __restrict__ gamma, const float* __restrict__ beta,
                  const float* __restrict__ dvec) {
    int j = blockIdx.x * 8 + (threadIdx.x >> 5);
    if (j >= S) return;
    int ln = threadIdx.x & 31;
    const float2* pt = g_part + (size_t)j * NC;
    float s = 0.f, ss = 0.f;
    #pragma unroll
    for (int i = 0; i < 16; i++) {
        float2 v = pt[ln + 32 * i];
        s += v.x; ss += v.y;
    }
    #pragma unroll
    for (int o = 16; o; o >>= 1) {
        s  += __shfl_xor_sync(0xffffffffu, s,  o);
        ss += __shfl_xor_sync(0xffffffffu, ss, o);
    }
    if (ln == 0) {
        float m   = s * (1.f / 8192.f);
        float var = ss * (1.f / 8192.f) - m * m;
        float rstd = rsqrtf(var + 1e-5f);
        g_stat[j] = make_float4(m, gamma[j] * rstd, beta[j],
                                dvec ? dvec[j] : 0.f);
    }
}

// ---------------- output head: applies layer-6 BN/tanh/skip inline -----------
__global__ __launch_bounds__(512)
void out_kernel(int ssel, const float* __restrict__ fasm,
                const float* __restrict__ wout, const float* __restrict__ bout,
                float* __restrict__ out) {
    __shared__ float fw[S];
    for (int i = threadIdx.x; i < S; i += blockDim.x) fw[i] = fasm[i] * wout[i];
    __syncthreads();
    int b = blockIdx.x * blockDim.x + threadIdx.x;
    int c = b >> 4, lane = b & 15;
    const float*  Yb = g_Y + (size_t)c * S16 + lane;
    const __half* sb = getact(ssel) + (size_t)c * S16 + lane;
    float s = *bout;
    for (int jj = 0; jj < S; jj++) {
        float f = fw[jj];
        if (f != 0.f) {
            float4 st = g_stat[jj];
            float y  = Yb[(size_t)jj * 16];
            float a5 = __half2float(sb[(size_t)jj * 16]);
            float a6 = tanhf((y - st.x) * st.y + st.z) + a5 * st.w;
            s += a6 * f;
        }
    }
    out[b] = s;
}

// ---------------- launch ------------------------------------------------------
extern "C" void kernel_launch(void* const* d_in, const int* in_sizes, int n_in,
                              void* d_out, int out_size) {
    const float* x     = (const float*)d_in[0];
    const float* lm0   = (const float*)d_in[1];
    const float* lm    = (const float*)d_in[2];
    const float* flm   = (const float*)d_in[3];
    const float* fasm  = (const float*)d_in[4];
    const float* W0    = (const float*)d_in[5];
    const float* W     = (const float*)d_in[7];
    const float* gamma = (const float*)d_in[9];
    const float* beta  = (const float*)d_in[10];
    const float* wout  = (const float*)d_in[11];
    const float* bout  = (const float*)d_in[12];
    float* out = (float*)d_out;
    // note: biases b0/b (d_in[6], d_in[8]) cancel exactly through training-mode BN

    cudaFuncSetAttribute(spmm_kernel, cudaFuncAttributeMaxDynamicSharedMemorySize,
                         S * SSTRIDE);

    // 1) build sparse structure (pad folded into fill)
    count_kernel<<<dim3((S + 127) / 128, NLAY, RSPLIT), 128>>>(lm0, lm);
    prefix_kernel<<<dim3((S + 127) / 128, NLAY), 128>>>();
    sort_kernel<<<dim3((S + 1023) / 1024, NLAY), 1024>>>();
    fill_kernel<<<dim3((NBP8 + 127) / 128, NLAY, RSPLIT), 128>>>(lm0, W0, lm, W);

    // 2) transpose x -> actA (fp16)
    xt_kernel<<<dim3((G + XT_TI - 1) / XT_TI, NC), 256>>>(x);

    // 3) layer 0: plain gather from actA -> Y0 + partials; stats0 (no skip)
    spmm_kernel<<<NGRID, 1024, G * SSTRIDE>>>(0, 0, 0, 0, G);
    stats_kernel<<<(S + 7) / 8, 256>>>(gamma, beta, nullptr);

    // 4) layers 1..6: fused BN/tanh/skip tile-load + gather; then stats_l
    for (int l = 1; l <= 6; l++) {
        int wsel = (l & 1) ? 1 : 0;   // h_{l-1} written to B for odd l
        int ssel = 1 - wsel;          // skip (h_{l-2}) read from the other
        spmm_kernel<<<NGRID, 1024, S * SSTRIDE>>>(1, wsel, ssel, l, S);
        stats_kernel<<<(S + 7) / 8, 256>>>(gamma + (size_t)l * S,
                                           beta + (size_t)l * S,
                                           flm + (size_t)(l - 1) * S);
    }

    // 5) output head (layer-6 activation computed inline; h_5 is in actA)
    out_kernel<<<16, 512>>>(0, fasm, wout, bout, out);
}

// round 9
// speedup vs baseline: 1.1074x; 1.1074x over previous
#include <cuda_runtime.h>
#include <cuda_fp16.h>

// Problem constants
#define S      2785
#define S16    (S * 16)
#define G      689
#define NC     512            // batch chunks of 16
#define CAP    192            // max nnz per column
#define CAPP   (CAP / 2)      // entry pairs
#define NLAY   7
#define RSPLIT 8
#define NW     88             // bitmap words per column (ceil(2785/32))
#define WPC    11             // words per RSPLIT chunk (88/8)
#define NB     349            // column blocks of 8
#define NBP8   (NB * 8)
#define NFULL  444            // CTAs 0..443: full chunks 0..443
#define NHALF  136            // CTAs 444..579: half-chunks of chunks 444..511
#define NGRID  (NFULL + NHALF)
#define SSTRIDE 48            // smem bytes per slot (24 halfs) — R7 proven

// ---------------- device global scratch ---------------------------------------
__device__ __half    g_actA[(size_t)NC * S16];
__device__ __half    g_actB[(size_t)NC * S16];
__device__ float     g_Y[(size_t)NC * S16];
__device__ int4      g_be2[(size_t)NLAY * NB * CAPP * 8]; // paired entries [l][b][kp][g]
__device__ float2    g_part[(size_t)S * NC];
__device__ float4    g_stat[S];                  // {mean, gamma*rstd, beta, d}
__device__ unsigned  g_bits[(size_t)NLAY * NW * S];  // occupancy bitmaps [l][w][j]
__device__ int       g_cnt[NLAY * S];
__device__ int       g_off8[NLAY * RSPLIT * S];
__device__ int       g_perm[NLAY * NBP8];
__device__ int       g_scnt[NLAY * NBP8];
__device__ int       g_blkmax[NLAY * NB];

__device__ __forceinline__ __half* getact(int s) { return s == 0 ? g_actA : g_actB; }

// ---------------- build phase A: occupancy bitmaps (single scan of masks) ----
__global__ void bits_kernel(const float* __restrict__ lm0, const float* __restrict__ lm) {
    int l = blockIdx.y;
    int w = blockIdx.z;                         // word 0..87
    int j = blockIdx.x * 128 + threadIdx.x;
    if (j >= S) return;
    int rows = (l == 0) ? G : S;
    unsigned m = 0;
    int i0 = w * 32;
    if (i0 < rows) {
        const float* M = (l == 0) ? lm0 : lm + (size_t)(l - 1) * S * S;
        const float* Mr = M + (size_t)i0 * S + j;
        if (i0 + 32 <= rows) {
            #pragma unroll
            for (int k = 0; k < 32; k++)
                m |= (Mr[(size_t)k * S] != 0.f ? 1u : 0u) << k;
        } else {
            int n = rows - i0;
            for (int k = 0; k < n; k++)
                m |= (Mr[(size_t)k * S] != 0.f ? 1u : 0u) << k;
        }
    }
    g_bits[((size_t)l * NW + w) * S + j] = m;   // coalesced store
}

// ---------------- build phase B: per-chunk popc prefix ------------------------
__global__ void prefix_kernel() {
    int l = blockIdx.y;
    int j = blockIdx.x * 128 + threadIdx.x;
    if (j >= S) return;
    int off = 0;
    #pragma unroll
    for (int r = 0; r < RSPLIT; r++) {
        int c = 0;
        #pragma unroll
        for (int w = r * WPC; w < (r + 1) * WPC; w++)
            c += __popc(g_bits[((size_t)l * NW + w) * S + j]);
        g_off8[(l * RSPLIT + r) * S + j] = off;
        off += c;
    }
    g_cnt[l * S + j] = min(off, CAP);
}

// ---------------- build phase C: deterministic rank-sort (desc nnz, asc j) ---
#define S4 ((S + 3) / 4)
__global__ __launch_bounds__(1024)
void sort_kernel() {
    int l = blockIdx.y;
    __shared__ int4 scnt4[S4];
    int* scnt = (int*)scnt4;
    for (int j = threadIdx.x; j < S4 * 4; j += 1024)
        scnt[j] = (j < S) ? g_cnt[l * S + j] : -1;
    __syncthreads();

    int j = blockIdx.x * 1024 + threadIdx.x;
    if (j < S) {
        int c = scnt[j];
        int pos = 0;
        for (int q = 0; q < S4; q++) {
            int4 v = scnt4[q];
            int b0 = 4 * q;
            pos += (v.x > c) || (v.x == c && b0 + 0 < j);
            pos += (v.y > c) || (v.y == c && b0 + 1 < j);
            pos += (v.z > c) || (v.z == c && b0 + 2 < j);
            pos += (v.w > c) || (v.w == c && b0 + 3 < j);
        }
        g_perm[l * NBP8 + pos] = j;
        g_scnt[l * NBP8 + pos] = c;
        if ((pos & 7) == 0) g_blkmax[l * NB + (pos >> 3)] = c;
    }
    if (blockIdx.x == 0)
        for (int p = S + threadIdx.x; p < NBP8; p += 1024) {
            g_perm[l * NBP8 + p] = -1;
            g_scnt[l * NBP8 + p] = 0;
        }
}

// ---------------- build phase D: fill entries from bitmaps + zero-pad --------
__global__ void fill_kernel(const float* __restrict__ W0, const float* __restrict__ Wl) {
    int l = blockIdx.y, r = blockIdx.z;
    int p = blockIdx.x * 128 + threadIdx.x;
    if (p >= NBP8) return;
    int j = g_perm[l * NBP8 + p];
    int b = p >> 3, g = p & 7;
    int2* e2 = (int2*)g_be2;
    size_t bi = (size_t)(l * NB + b) * CAPP;
    int km = g_blkmax[l * NB + b];
    int kmpad = ((km + 1) >> 1) << 1;

    if (j < 0) {   // pad column: zero everything once
        if (r == RSPLIT - 1)
            for (int k = 0; k < kmpad; k++)
                e2[((bi + (k >> 1)) * 8 + g) * 2 + (k & 1)] = make_int2(0, 0);
        return;
    }
    const float* Wm = (l == 0) ? W0 : Wl + (size_t)(l - 1) * S * S;
    int o = g_off8[(l * RSPLIT + r) * S + j];
    for (int w = r * WPC; w < (r + 1) * WPC; w++) {
        unsigned m = g_bits[((size_t)l * NW + w) * S + j];
        int ibase = w * 32;
        while (m) {
            int k = __ffs(m) - 1;
            m &= m - 1;
            int i = ibase + k;
            if (o < CAP) {
                float wv = Wm[(size_t)i * S + j];
                e2[((bi + (o >> 1)) * 8 + g) * 2 + (o & 1)] =
                    make_int2(i * SSTRIDE, __float_as_int(wv));
            }
            o++;
        }
    }
    if (r == RSPLIT - 1) {
        int start = g_scnt[l * NBP8 + p];    // column total nnz (<= CAP)
        for (int k = start; k < kmpad; k++)
            e2[((bi + (k >> 1)) * 8 + g) * 2 + (k & 1)] = make_int2(0, 0);
    }
}

// ---------------- coalesced transpose x [B,G] -> [NC][G][16] fp16 ------------
#define XT_TI 128
__global__ __launch_bounds__(256)
void xt_kernel(const float* __restrict__ x) {
    __shared__ float tile[16][XT_TI + 1];
    int c  = blockIdx.y;
    int i0 = blockIdx.x * XT_TI;
    int t  = threadIdx.x;
    int col = t & 127;
    #pragma unroll
    for (int rr = 0; rr < 8; rr++) {
        int row = rr * 2 + (t >> 7);
        int i = i0 + col;
        tile[row][col] = (i < G) ? x[(size_t)(c * 16 + row) * G + i] : 0.f;
    }
    __syncthreads();
    int lane = t & 15;
    #pragma unroll
    for (int bq = 0; bq < 8; bq++) {
        int ii = (t >> 4) + bq * 16;
        int i = i0 + ii;
        if (i < G)
            g_actA[(size_t)c * (G * 16) + (size_t)i * 16 + lane] =
                __float2half_rn(tile[lane][ii]);
    }
}

// ---------------- fused SpMM (R7-proven): BN/tanh/skip tile-load + gather ----
__global__ __launch_bounds__(1024, 1)
void spmm_kernel(int mode, int wsel, int ssel, int layer, int n_slots) {
    extern __shared__ char xs[];

    int w     = threadIdx.x >> 5;
    int lane  = threadIdx.x & 31;
    int g     = lane >> 2;
    int lane4 = lane & 3;
    const char* xsb = xs + lane4 * 8;

    int bid = blockIdx.x;
    int c, b0, bstep;
    if (bid < NFULL) { c = bid; b0 = w; bstep = 32; }
    else {
        int t = bid - NFULL;
        c = NFULL + (t >> 1);
        b0 = (t & 1) + 2 * w;
        bstep = 64;
    }

    if (mode == 0) {
        const uint4* src = (const uint4*)(g_actA + (size_t)c * n_slots * 16);
        int nq = n_slots * 2;
        for (int t = threadIdx.x; t < nq; t += 1024) {
            int slot = t >> 1, q = t & 1;
            *(uint4*)(xs + slot * SSTRIDE + q * 16) = src[t];
        }
    } else {
        const float* Yc = g_Y + (size_t)c * S16;
        const __half* skp = getact(ssel) + (size_t)c * S16;
        __half* actw = getact(wsel) + (size_t)c * S16;
        for (int q = threadIdx.x; q < S * 4; q += 1024) {
            int slot = q >> 2, quad = q & 3;
            float4 st = g_stat[slot];                 // {m, gs, bt, d}
            float4 y  = *(const float4*)(Yc + slot * 16 + quad * 4);
            uint2 sk  = *(const uint2*)(skp + slot * 16 + quad * 4);
            float2 s0 = __half22float2(*(__half2*)&sk.x);
            float2 s1 = __half22float2(*(__half2*)&sk.y);
            float a0 = tanhf((y.x - st.x) * st.y + st.z) + s0.x * st.w;
            float a1 = tanhf((y.y - st.x) * st.y + st.z) + s0.y * st.w;
            float a2 = tanhf((y.z - st.x) * st.y + st.z) + s1.x * st.w;
            float a3 = tanhf((y.w - st.x) * st.y + st.z) + s1.y * st.w;
            __half2 h0 = __floats2half2_rn(a0, a1);
            __half2 h1 = __floats2half2_rn(a2, a3);
            uint2 pk;
            *(__half2*)&pk.x = h0;
            *(__half2*)&pk.y = h1;
            *(uint2*)(xs + slot * SSTRIDE + quad * 8) = pk;
            *(uint2*)(actw + slot * 16 + quad * 4) = pk;  // dup writes on split chunks: identical bits
        }
    }
    __syncthreads();

    float* yb = g_Y + (size_t)c * S16;
    for (int b = b0; b < NB; b += bstep) {
        int pp = b * 8 + g;
        int j  = g_perm[layer * NBP8 + pp];
        int km = g_blkmax[layer * NB + b];
        int kmp = (km + 1) >> 1;
        const int4* ep4 = g_be2 + (size_t)(layer * NB + b) * CAPP * 8 + g;
        float4 acc = make_float4(0.f, 0.f, 0.f, 0.f);
        if (kmp > 0) {
            // 1-deep pipeline: gathers for pair k issued before FMAs of pair k-1
            int4 e = ep4[0];
            uint2 r0 = *(const uint2*)(xsb + e.x);
            uint2 r1 = *(const uint2*)(xsb + e.z);
            for (int kp = 0; kp + 1 < kmp; kp++) {
                int4 en = ep4[(size_t)(kp + 1) * 8];
                uint2 n0 = *(const uint2*)(xsb + en.x);
                uint2 n1 = *(const uint2*)(xsb + en.z);
                float w0 = __int_as_float(e.y);
                float w1 = __int_as_float(e.w);
                float2 a0 = __half22float2(*(__half2*)&r0.x);
                float2 a1 = __half22float2(*(__half2*)&r0.y);
                float2 b0v = __half22float2(*(__half2*)&r1.x);
                float2 b1v = __half22float2(*(__half2*)&r1.y);
                acc.x = fmaf(w0, a0.x, acc.x);
                acc.y = fmaf(w0, a0.y, acc.y);
                acc.z = fmaf(w0, a1.x, acc.z);
                acc.w = fmaf(w0, a1.y, acc.w);
                acc.x = fmaf(w1, b0v.x, acc.x);
                acc.y = fmaf(w1, b0v.y, acc.y);
                acc.z = fmaf(w1, b1v.x, acc.z);
                acc.w = fmaf(w1, b1v.y, acc.w);
                e = en; r0 = n0; r1 = n1;
            }
            {
                float w0 = __int_as_float(e.y);
                float w1 = __int_as_float(e.w);
                float2 a0 = __half22float2(*(__half2*)&r0.x);
                float2 a1 = __half22float2(*(__half2*)&r0.y);
                float2 b0v = __half22float2(*(__half2*)&r1.x);
                float2 b1v = __half22float2(*(__half2*)&r1.y);
                acc.x = fmaf(w0, a0.x, acc.x);
                acc.y = fmaf(w0, a0.y, acc.y);
                acc.z = fmaf(w0, a1.x, acc.z);
                acc.w = fmaf(w0, a1.y, acc.w);
                acc.x = fmaf(w1, b0v.x, acc.x);
                acc.y = fmaf(w1, b0v.y, acc.y);
                acc.z = fmaf(w1, b1v.x, acc.z);
                acc.w = fmaf(w1, b1v.y, acc.w);
            }
        }
        // BN partials: shuffles MUST run convergent (pad lanes j==-1 included).
        float s  = acc.x + acc.y + acc.z + acc.w;
        float ss = acc.x * acc.x + acc.y * acc.y + acc.z * acc.z + acc.w * acc.w;
        s  += __shfl_xor_sync(0xffffffffu, s, 1);
        ss += __shfl_xor_sync(0xffffffffu, ss, 1);
        s  += __shfl_xor_sync(0xffffffffu, s, 2);
        ss += __shfl_xor_sync(0xffffffffu, ss, 2);
        if (j >= 0) {
            *(float4*)(yb + (size_t)j * 16 + lane4 * 4) = acc;
            if (lane4 == 0)
                g_part[(size_t)j * NC + c] = make_float2(s, ss);
        }
    }
}

// ---------------- stats: fold partials + gamma/beta/diag into float4 ---------
__global__ __launch_bounds__(256)
void stats_kernel(const float* __restrict__ gamma, const float* __restrict__ beta,
                  const float* __restrict__ dvec) {
    int j = blockIdx.x * 8 + (threadIdx.x >> 5);
    if (j >= S) return;
    int ln = threadIdx.x & 31;
    const float2* pt = g_part + (size_t)j * NC;
    float s = 0.f, ss = 0.f;
    #pragma unroll
    for (int i = 0; i < 16; i++) {
        float2 v = pt[ln + 32 * i];
        s += v.x; ss += v.y;
    }
    #pragma unroll
    for (int o = 16; o; o >>= 1) {
        s  += __shfl_xor_sync(0xffffffffu, s,  o);
        ss += __shfl_xor_sync(0xffffffffu, ss, o);
    }
    if (ln == 0) {
        float m   = s * (1.f / 8192.f);
        float var = ss * (1.f / 8192.f) - m * m;
        float rstd = rsqrtf(var + 1e-5f);
        g_stat[j] = make_float4(m, gamma[j] * rstd, beta[j],
                                dvec ? dvec[j] : 0.f);
    }
}

// ---------------- output head: applies layer-6 BN/tanh/skip inline -----------
__global__ __launch_bounds__(512)
void out_kernel(int ssel, const float* __restrict__ fasm,
                const float* __restrict__ wout, const float* __restrict__ bout,
                float* __restrict__ out) {
    __shared__ float fw[S];
    for (int i = threadIdx.x; i < S; i += blockDim.x) fw[i] = fasm[i] * wout[i];
    __syncthreads();
    int b = blockIdx.x * blockDim.x + threadIdx.x;
    int c = b >> 4, lane = b & 15;
    const float*  Yb = g_Y + (size_t)c * S16 + lane;
    const __half* sb = getact(ssel) + (size_t)c * S16 + lane;
    float s = *bout;
    for (int jj = 0; jj < S; jj++) {
        float f = fw[jj];
        if (f != 0.f) {
            float4 st = g_stat[jj];
            float y  = Yb[(size_t)jj * 16];
            float a5 = __half2float(sb[(size_t)jj * 16]);
            float a6 = tanhf((y - st.x) * st.y + st.z) + a5 * st.w;
            s += a6 * f;
        }
    }
    out[b] = s;
}

// ---------------- launch ------------------------------------------------------
extern "C" void kernel_launch(void* const* d_in, const int* in_sizes, int n_in,
                              void* d_out, int out_size) {
    const float* x     = (const float*)d_in[0];
    const float* lm0   = (const float*)d_in[1];
    const float* lm    = (const float*)d_in[2];
    const float* flm   = (const float*)d_in[3];
    const float* fasm  = (const float*)d_in[4];
    const float* W0    = (const float*)d_in[5];
    const float* W     = (const float*)d_in[7];
    const float* gamma = (const float*)d_in[9];
    const float* beta  = (const float*)d_in[10];
    const float* wout  = (const float*)d_in[11];
    const float* bout  = (const float*)d_in[12];
    float* out = (float*)d_out;
    // note: biases b0/b (d_in[6], d_in[8]) cancel exactly through training-mode BN

    cudaFuncSetAttribute(spmm_kernel, cudaFuncAttributeMaxDynamicSharedMemorySize,
                         S * SSTRIDE);

    // 1) build sparse structure: single mask scan -> bitmaps -> prefix/sort/fill
    bits_kernel<<<dim3((S + 127) / 128, NLAY, NW), 128>>>(lm0, lm);
    prefix_kernel<<<dim3((S + 127) / 128, NLAY), 128>>>();
    sort_kernel<<<dim3((S + 1023) / 1024, NLAY), 1024>>>();
    fill_kernel<<<dim3((NBP8 + 127) / 128, NLAY, RSPLIT), 128>>>(W0, W);

    // 2) transpose x -> actA (fp16)
    xt_kernel<<<dim3((G + XT_TI - 1) / XT_TI, NC), 256>>>(x);

    // 3) layer 0: plain gather from actA -> Y0 + partials; stats0 (no skip)
    spmm_kernel<<<NGRID, 1024, G * SSTRIDE>>>(0, 0, 0, 0, G);
    stats_kernel<<<(S + 7) / 8, 256>>>(gamma, beta, nullptr);

    // 4) layers 1..6: fused BN/tanh/skip tile-load + gather; then stats_l
    for (int l = 1; l <= 6; l++) {
        int wsel = (l & 1) ? 1 : 0;   // h_{l-1} written to B for odd l
        int ssel = 1 - wsel;          // skip (h_{l-2}) read from the other
        spmm_kernel<<<NGRID, 1024, S * SSTRIDE>>>(1, wsel, ssel, l, S);
        stats_kernel<<<(S + 7) / 8, 256>>>(gamma + (size_t)l * S,
                                           beta + (size_t)l * S,
                                           flm + (size_t)(l - 1) * S);
    }

    // 5) output head (layer-6 activation computed inline; h_5 is in actA)
    out_kernel<<<16, 512>>>(0, fasm, wout, bout, out);
}